// round 12
// baseline (speedup 1.0000x reference)
#include <cuda_runtime.h>
#include <cstdint>

#define B_DIM 64
#define N_DIM 1024
#define C_DIM 256
#define NTOK (B_DIM * N_DIM)
#define OUT_IDX  ((size_t)B_DIM * N_DIM * C_DIM)
#define OUT_LOSS (OUT_IDX + (size_t)B_DIM * N_DIM)
#define EPS_AMB 3e-4f
#define TOK 64
#define KTOT 3840

// vq tiling: 64 tokens resident x 128-code blocks, KC=32 channels per stage
#define TOKT 64
#define KC 32
// smem: zs [256][64] f32 = 64KB; B 2 x [32][128] f32 = 32KB; reduce 6KB
#define BB_BASE  65536
#define BB_BUF   16384
#define RED_BASE 98304
#define SM_DYN   104448

// ---- device scratch (no cudaMalloc allowed) ----
__device__ float g_cnorm[KTOT];
__device__ float g_partial[1024];
__device__ int   g_idx[NTOK];
__device__ int   g_amb[NTOK];
__device__ int   g_cnt;
__device__ float g_cbT[256 * KTOT];   // transposed codebooks: [c][global k]

// ---- helpers ----
__device__ __forceinline__ uint32_t smem_u32(const void* p) {
    uint32_t a;
    asm("{ .reg .u64 t; cvta.to.shared.u64 t, %1; cvt.u32.u64 %0, t; }" : "=r"(a) : "l"(p));
    return a;
}
#define CP16(dst, src)  asm volatile("cp.async.cg.shared.global [%0], [%1], 16;" :: "r"(dst), "l"(src) : "memory")
#define CP_COMMIT()     asm volatile("cp.async.commit_group;" ::: "memory")
#define CP_WAIT1()      asm volatile("cp.async.wait_group 1;" ::: "memory")
#define CP_WAIT0()      asm volatile("cp.async.wait_group 0;" ::: "memory")
#define FFMA2(acc, a, b) asm("fma.rn.f32x2 %0, %1, %2, %0;" : "+l"(acc) : "l"(a), "l"(b))
#define PACKDUP(out, v)  asm("mov.b64 %0, {%1, %1};" : "=l"(out) : "r"(v))

__device__ __forceinline__ void pick_cb(int e, const float* cb0, const float* cb1,
                                        const float* cb2, const float* cb3,
                                        const float*& cb, int& K, int& coff) {
    if (e == 0)      { cb = cb0; K = 256;  coff = 0;    }
    else if (e == 1) { cb = cb1; K = 512;  coff = 256;  }
    else if (e == 2) { cb = cb2; K = 1024; coff = 768;  }
    else             { cb = cb3; K = 2048; coff = 1792; }
}

// ---------------------------------------------------------------------------
// K0a: transpose codebooks into g_cbT[c][global_k]
// ---------------------------------------------------------------------------
__global__ void transpose_kernel(const float* __restrict__ cb0, const float* __restrict__ cb1,
                                 const float* __restrict__ cb2, const float* __restrict__ cb3)
{
    int idx = blockIdx.x * 256 + threadIdx.x;
    int row = idx >> 6, c4 = idx & 63;
    const float* base; int local;
    if (row < 256)       { base = cb0; local = row;        }
    else if (row < 768)  { base = cb1; local = row - 256;  }
    else if (row < 1792) { base = cb2; local = row - 768;  }
    else                 { base = cb3; local = row - 1792; }
    float4 v = ((const float4*)(base + (size_t)local * C_DIM))[c4];
    float x[4] = {v.x, v.y, v.z, v.w};
    #pragma unroll
    for (int i = 0; i < 4; i++)
        g_cbT[(size_t)(c4 * 4 + i) * KTOT + row] = x[i];
}

// ---------------------------------------------------------------------------
// K0b: codebook row norms (fp64 -> fp32) + reset ambiguous counter
// ---------------------------------------------------------------------------
__global__ void cnorm_kernel(const float* __restrict__ cb0, const float* __restrict__ cb1,
                             const float* __restrict__ cb2, const float* __restrict__ cb3)
{
    if (blockIdx.x == 0 && threadIdx.x == 0) g_cnt = 0;
    int row  = blockIdx.x * 8 + (threadIdx.x >> 5);
    int lane = threadIdx.x & 31;
    const float* base; int local;
    if (row < 256)       { base = cb0; local = row;        }
    else if (row < 768)  { base = cb1; local = row - 256;  }
    else if (row < 1792) { base = cb2; local = row - 768;  }
    else                 { base = cb3; local = row - 1792; }
    const float4* p = (const float4*)(base + (size_t)local * C_DIM);
    double s = 0.0;
    #pragma unroll
    for (int i = 0; i < 2; i++) {
        float4 v = p[lane + i * 32];
        s += (double)v.x * v.x + (double)v.y * v.y + (double)v.z * v.z + (double)v.w * v.w;
    }
    #pragma unroll
    for (int o = 16; o; o >>= 1) s += __shfl_xor_sync(0xffffffffu, s, o);
    if (lane == 0) g_cnorm[row] = (float)s;
}

// nop: aligns the main GEMM to user-launch index 3 for the fixed ncu -s window
__global__ void nop_kernel() {}

// ---------------------------------------------------------------------------
// K1: resident-z f32x2 distance GEMM. CTA: 64 tokens x full K, 256 threads,
// 2 CTAs/SM. Thread: 8 tokens (lane&7) x 4 codes (warp*16 + (lane>>3)*4).
// z resident [256c][64t]; B streamed 128-code blocks, KC=32 stages, cp.async,
// double-buffered with BOTH barriers (prefetch-overwrite race fixed).
// score(k) = ||c_k||^2 - 2 z.c_k ; per-token top-2 + ambiguity flags.
// ---------------------------------------------------------------------------
__global__ __launch_bounds__(256, 2) void vq_gemm(
    const float* __restrict__ z_e, const int* __restrict__ expert_idx)
{
    extern __shared__ __align__(16) char dsm[];
    const uint32_t sa = smem_u32(dsm);

    const int tid = threadIdx.x, w = tid >> 5, lane = tid & 31;
    const int lt = lane & 7;          // token group: tokens lt*8..lt*8+7
    const int lc = lane >> 3;         // code subgroup 0..3
    const int b = blockIdx.y, t0 = blockIdx.x * TOKT;

    int e = expert_idx[b];
    int K, coff;
    if (e == 0)      { K = 256;  coff = 0;    }
    else if (e == 1) { K = 512;  coff = 256;  }
    else if (e == 2) { K = 1024; coff = 768;  }
    else             { K = 2048; coff = 1792; }

    // ---- stage z resident: zs[c][t], once ----
    const float4* zin = (const float4*)(z_e + ((size_t)b * N_DIM + t0) * C_DIM);
    float* zs = (float*)dsm;
    #pragma unroll
    for (int it = 0; it < 16; it++) {
        int idx = it * 256 + tid;              // 0..4095
        int t = idx >> 6, q = idx & 63;
        float4 v = zin[t * 64 + q];
        zs[(q * 4 + 0) * TOKT + t] = v.x;
        zs[(q * 4 + 1) * TOKT + t] = v.y;
        zs[(q * 4 + 2) * TOKT + t] = v.z;
        zs[(q * 4 + 3) * TOKT + t] = v.w;
    }

    // ---- B stage: [32 c][128 codes] = 16KB, 4 CP16/thread ----
    auto cpB = [&](int s) {
        int kb = (s >> 3) << 7;                // code block base
        int cs = (s & 7) * 32;                 // channel base
        uint32_t bbuf = sa + BB_BASE + (uint32_t)((s & 1) * BB_BUF);
        const float* src0 = g_cbT + (size_t)cs * KTOT + coff + kb;
        #pragma unroll
        for (int i = 0; i < 4; i++) {
            int fid = tid * 4 + i;             // 0..1023
            int cc = fid >> 5, seg = fid & 31;
            CP16(bbuf + (uint32_t)(cc * 512 + seg * 16),
                 src0 + (size_t)cc * KTOT + seg * 4);
        }
    };

    cpB(0); CP_COMMIT();

    unsigned long long acc[4][4];              // [token pair][code]
    float v1[8], v2[8]; int i1[8];
    #pragma unroll
    for (int r = 0; r < 8; r++) { v1[r] = 3.4e38f; v2[r] = 3.4e38f; i1[r] = 0; }

    const int cw = w * 16 + lc * 4;            // code offset within block
    const int S = (K >> 7) * 8;                // 8 stages per 128-code block

    for (int s = 0; s < S; s++) {
        if (s + 1 < S) { cpB(s + 1); CP_COMMIT(); CP_WAIT1(); }
        else           { CP_WAIT0(); }
        __syncthreads();                       // buffer (s&1) ready (+ zs on s=0)

        if ((s & 7) == 0) {
            #pragma unroll
            for (int tp = 0; tp < 4; tp++)
                #pragma unroll
                for (int j = 0; j < 4; j++) acc[tp][j] = 0ull;
        }

        const char* zb = dsm + ((s & 7) * 32) * (TOKT * 4) + lt * 32;
        const char* bb = dsm + BB_BASE + (s & 1) * BB_BUF + cw * 4;
        #pragma unroll
        for (int k = 0; k < KC; k++) {
            ulonglong2 a01 = *(const ulonglong2*)(zb + k * (TOKT * 4));
            ulonglong2 a23 = *(const ulonglong2*)(zb + k * (TOKT * 4) + 16);
            float4 bv = *(const float4*)(bb + k * 512);
            unsigned long long at[4] = {a01.x, a01.y, a23.x, a23.y};
            unsigned long long bd[4];
            PACKDUP(bd[0], __float_as_uint(bv.x));
            PACKDUP(bd[1], __float_as_uint(bv.y));
            PACKDUP(bd[2], __float_as_uint(bv.z));
            PACKDUP(bd[3], __float_as_uint(bv.w));
            #pragma unroll
            for (int tp = 0; tp < 4; tp++)
                #pragma unroll
                for (int j = 0; j < 4; j++)
                    FFMA2(acc[tp][j], at[tp], bd[j]);
        }

        if ((s & 7) == 7) {                    // code-block epilogue
            int kb = (s >> 3) << 7;
            float4 cn = __ldg((const float4*)(g_cnorm + coff + kb + cw));
            float cna[4] = {cn.x, cn.y, cn.z, cn.w};
            #pragma unroll
            for (int j = 0; j < 4; j++) {
                int kk = kb + cw + j;
                #pragma unroll
                for (int tp = 0; tp < 4; tp++) {
                    float lo = __uint_as_float((uint32_t)acc[tp][j]);
                    float hi = __uint_as_float((uint32_t)(acc[tp][j] >> 32));
                    float s0 = fmaf(-2.f, lo, cna[j]);
                    float s1 = fmaf(-2.f, hi, cna[j]);
                    int r0 = tp * 2, r1 = tp * 2 + 1;
                    if (s0 < v1[r0]) { v2[r0] = v1[r0]; v1[r0] = s0; i1[r0] = kk; }
                    else             { v2[r0] = fminf(v2[r0], s0); }
                    if (s1 < v1[r1]) { v2[r1] = v1[r1]; v1[r1] = s1; i1[r1] = kk; }
                    else             { v2[r1] = fminf(v2[r1], s1); }
                }
            }
        }
        __syncthreads();   // all readers done with buffer (s&1) before cpB(s+2) overwrites it
    }

    // merge over lc (lane bits 3,4): lanes share tokens, disjoint codes
    #pragma unroll
    for (int o = 8; o <= 16; o <<= 1) {
        #pragma unroll
        for (int r = 0; r < 8; r++) {
            float ov1 = __shfl_xor_sync(0xffffffffu, v1[r], o);
            int   oi1 = __shfl_xor_sync(0xffffffffu, i1[r], o);
            float ov2 = __shfl_xor_sync(0xffffffffu, v2[r], o);
            float hi = fmaxf(v1[r], ov1);
            float nv2 = fminf(fminf(v2[r], ov2), hi);
            if (ov1 < v1[r] || (ov1 == v1[r] && oi1 < i1[r])) { v1[r] = ov1; i1[r] = oi1; }
            v2[r] = nv2;
        }
    }
    // cross-warp: write per-warp per-token top2 to smem, then 64 threads merge
    float* rv1 = (float*)(dsm + RED_BASE);
    float* rv2 = rv1 + 512;
    int*   ri1 = (int*)(rv2 + 512);
    if (lc == 0) {
        #pragma unroll
        for (int r = 0; r < 8; r++) {
            int t = lt * 8 + r;
            rv1[w * 64 + t] = v1[r];
            rv2[w * 64 + t] = v2[r];
            ri1[w * 64 + t] = i1[r];
        }
    }
    __syncthreads();
    if (tid < TOKT) {
        float bv1 = rv1[tid], bv2 = rv2[tid]; int bi1 = ri1[tid];
        #pragma unroll
        for (int ww = 1; ww < 8; ww++) {
            float ov1 = rv1[ww * 64 + tid], ov2 = rv2[ww * 64 + tid];
            int   oi1 = ri1[ww * 64 + tid];
            float hi = fmaxf(bv1, ov1);
            float nv2 = fminf(fminf(bv2, ov2), hi);
            if (ov1 < bv1 || (ov1 == bv1 && oi1 < bi1)) { bv1 = ov1; bi1 = oi1; }
            bv2 = nv2;
        }
        int tok = b * N_DIM + t0 + tid;
        g_idx[tok] = bi1;
        if (bv2 - bv1 <= EPS_AMB) {
            int pos = atomicAdd(&g_cnt, 1);
            g_amb[pos] = tok;
        }
    }
}

// ---------------------------------------------------------------------------
// K2: exact resolver (validated round 2): emulate reference fp32 rounding
// ---------------------------------------------------------------------------
__global__ __launch_bounds__(256) void resolve_kernel(
    const float* __restrict__ z_e, const int* __restrict__ expert_idx,
    const float* __restrict__ cb0, const float* __restrict__ cb1,
    const float* __restrict__ cb2, const float* __restrict__ cb3)
{
    __shared__ float zrow[8][C_DIM];
    const int wid = threadIdx.x >> 5, lane = threadIdx.x & 31;
    const int gw = blockIdx.x * 8 + wid;
    const int nw = gridDim.x * 8;
    const int cnt = g_cnt;

    for (int it = gw; it < cnt; it += nw) {
        int tok = g_amb[it];
        int b = tok >> 10;
        const float* cb; int K, coff;
        pick_cb(expert_idx[b], cb0, cb1, cb2, cb3, cb, K, coff);

        const float4* zr = (const float4*)(z_e + (size_t)tok * C_DIM);
        #pragma unroll
        for (int r = 0; r < 2; r++) {
            float4 v = zr[lane + r * 32];
            int c = (lane + r * 32) * 4;
            zrow[wid][c + 0] = v.x; zrow[wid][c + 1] = v.y;
            zrow[wid][c + 2] = v.z; zrow[wid][c + 3] = v.w;
        }
        __syncwarp();

        double zn = 0.0;
        #pragma unroll
        for (int c = 0; c < 8; c++) {
            double z = (double)zrow[wid][lane * 8 + c];
            zn += z * z;
        }
        #pragma unroll
        for (int o = 16; o; o >>= 1) zn += __shfl_xor_sync(0xffffffffu, zn, o);

        const double invGs = (zn >= 256.0) ? 32768.0 : 65536.0;
        const double Gs = 1.0 / invGs;

        double bestm = 1e300; int besti = 0x7fffffff;
        for (int k0 = 0; k0 < K; k0 += 32) {
            int k = k0 + lane;
            const float* cr = cb + (size_t)k * C_DIM;
            float acc = 0.f;
            #pragma unroll 8
            for (int c = 0; c < C_DIM; c++)
                acc = fmaf(zrow[wid][c], __ldg(&cr[c]), acc);
            float cn32 = __ldg(&g_cnorm[coff + k]);
            double dot2 = 2.0 * (double)acc;
            double d = zn + (double)cn32 - dot2;
            double invGd = (d >= 256.0) ? 32768.0 : 65536.0;
            double Gd = 1.0 / invGd;
            double m = rint((double)cn32 * invGs) * Gs - rint(dot2 * invGd) * Gd;
            if (m < bestm || (m == bestm && k < besti)) { bestm = m; besti = k; }
        }
        #pragma unroll
        for (int o = 16; o; o >>= 1) {
            double om = __shfl_xor_sync(0xffffffffu, bestm, o);
            int    oi = __shfl_xor_sync(0xffffffffu, besti, o);
            if (om < bestm || (om == bestm && oi < besti)) { bestm = om; besti = oi; }
        }
        if (lane == 0) g_idx[tok] = besti;
    }
}

// ---------------------------------------------------------------------------
// K3: gather z_q, straight-through, indices output, SSE partials
// ---------------------------------------------------------------------------
__global__ __launch_bounds__(256) void output_kernel(
    const float* __restrict__ z_e, const int* __restrict__ expert_idx,
    const float* __restrict__ cb0, const float* __restrict__ cb1,
    const float* __restrict__ cb2, const float* __restrict__ cb3,
    float* __restrict__ out)
{
    __shared__ float wsum[8];
    const int tid = threadIdx.x;
    const int b   = blockIdx.y;
    const int t0  = blockIdx.x * TOK;

    const float* cb; int K, coff;
    pick_cb(expert_idx[b], cb0, cb1, cb2, cb3, cb, K, coff);

    const float4* zin = (const float4*)(z_e + ((size_t)b * N_DIM + t0) * C_DIM);

    if (tid < TOK) {
        int idx = g_idx[b * N_DIM + t0 + tid];
        out[OUT_IDX + (size_t)b * N_DIM + t0 + tid] = (float)idx;
    }

    const int warp = tid >> 5, lane = tid & 31;
    float sq = 0.f;
    for (int s8 = 0; s8 < 8; s8++) {
        int t = warp * 8 + s8;
        int idx = g_idx[b * N_DIM + t0 + t];
        const float4* crow = (const float4*)(cb + (size_t)idx * C_DIM);
        const float4* zrow = zin + (size_t)t * 64;
        float4* orow = (float4*)(out + ((size_t)b * N_DIM + t0 + t) * C_DIM);
        #pragma unroll
        for (int r = 0; r < 2; r++) {
            int c4 = lane + r * 32;
            float4 q = crow[c4], z = zrow[c4];
            float dx = q.x - z.x, dy = q.y - z.y, dz = q.z - z.z, dw = q.w - z.w;
            sq += dx * dx + dy * dy + dz * dz + dw * dw;
            float4 o; o.x = z.x + dx; o.y = z.y + dy; o.z = z.z + dz; o.w = z.w + dw;
            orow[c4] = o;
        }
    }
    #pragma unroll
    for (int o = 16; o; o >>= 1) sq += __shfl_xor_sync(0xffffffffu, sq, o);
    if (lane == 0) wsum[warp] = sq;
    __syncthreads();
    if (tid == 0) {
        float tot = 0.f;
        #pragma unroll
        for (int w = 0; w < 8; w++) tot += wsum[w];
        g_partial[blockIdx.y * 16 + blockIdx.x] = tot;
    }
}

// ---------------------------------------------------------------------------
// K4: vq_loss = 1.25 * SSE / 2^32
// ---------------------------------------------------------------------------
__global__ void finalize_kernel(float* __restrict__ out)
{
    __shared__ float s[256];
    float a = 0.f;
    for (int i = threadIdx.x; i < 1024; i += 256) a += g_partial[i];
    s[threadIdx.x] = a;
    __syncthreads();
    for (int o = 128; o; o >>= 1) {
        if (threadIdx.x < o) s[threadIdx.x] += s[threadIdx.x + o];
        __syncthreads();
    }
    if (threadIdx.x == 0)
        out[OUT_LOSS] = s[0] * (float)(1.25 / 4294967296.0);
}

// ---------------------------------------------------------------------------
extern "C" void kernel_launch(void* const* d_in, const int* in_sizes, int n_in,
                              void* d_out, int out_size)
{
    const float* z_e        = (const float*)d_in[0];
    const int*   expert_idx = (const int*)  d_in[1];
    const float* cb0        = (const float*)d_in[2];
    const float* cb1        = (const float*)d_in[3];
    const float* cb2        = (const float*)d_in[4];
    const float* cb3        = (const float*)d_in[5];
    float* out = (float*)d_out;

    cudaFuncSetAttribute(vq_gemm, cudaFuncAttributeMaxDynamicSharedMemorySize, SM_DYN);

    transpose_kernel<<<960, 256>>>(cb0, cb1, cb2, cb3);   // user launch 0
    cnorm_kernel<<<480, 256>>>(cb0, cb1, cb2, cb3);       // user launch 1
    nop_kernel<<<1, 32>>>();                              // user launch 2 (ncu align)

    dim3 gmain(N_DIM / TOKT, B_DIM);
    vq_gemm<<<gmain, 256, SM_DYN>>>(z_e, expert_idx);     // user launch 3 -> profiled

    resolve_kernel<<<128, 256>>>(z_e, expert_idx, cb0, cb1, cb2, cb3);

    dim3 gout(N_DIM / TOK, B_DIM);
    output_kernel<<<gout, 256>>>(z_e, expert_idx, cb0, cb1, cb2, cb3, out);

    finalize_kernel<<<1, 256>>>(out);
}

// round 13
// speedup vs baseline: 1.1776x; 1.1776x over previous
#include <cuda_runtime.h>
#include <cstdint>

#define B_DIM 64
#define N_DIM 1024
#define C_DIM 256
#define NTOK (B_DIM * N_DIM)
#define OUT_IDX  ((size_t)B_DIM * N_DIM * C_DIM)
#define OUT_LOSS (OUT_IDX + (size_t)B_DIM * N_DIM)
#define EPS_AMB 3e-4f
#define TOK 64
#define KTOT 3840

// vq tiling: 64 tokens resident x 256-code blocks, KC=8 channels per stage,
// 3-stage cp.async ring, thread tile 8 tok (4 f32x2 pairs) x 8 codes.
#define TOKT 64
#define KC 8
#define BB_BASE 65536      // after zs (64KB)
#define BB_BUF  8192       // 8 ch x 256 codes x 4B
#define SM_DYN  90112      // 64KB zs + 3 x 8KB B (reduce arrays alias B at end)

// ---- device scratch (no cudaMalloc allowed) ----
__device__ float g_cnorm[KTOT];
__device__ float g_partial[1024];
__device__ int   g_idx[NTOK];
__device__ int   g_amb[NTOK];
__device__ int   g_cnt;
__device__ float g_cbT[256 * KTOT];   // transposed codebooks: [c][global k]

// ---- helpers ----
__device__ __forceinline__ uint32_t smem_u32(const void* p) {
    uint32_t a;
    asm("{ .reg .u64 t; cvta.to.shared.u64 t, %1; cvt.u32.u64 %0, t; }" : "=r"(a) : "l"(p));
    return a;
}
#define CP16(dst, src)  asm volatile("cp.async.cg.shared.global [%0], [%1], 16;" :: "r"(dst), "l"(src) : "memory")
#define CP_COMMIT()     asm volatile("cp.async.commit_group;" ::: "memory")
#define CP_WAIT1()      asm volatile("cp.async.wait_group 1;" ::: "memory")
#define FFMA2(acc, a, b) asm("fma.rn.f32x2 %0, %1, %2, %0;" : "+l"(acc) : "l"(a), "l"(b))
#define PACKDUP(out, v)  asm("mov.b64 %0, {%1, %1};" : "=l"(out) : "r"(v))

__device__ __forceinline__ void pick_cb(int e, const float* cb0, const float* cb1,
                                        const float* cb2, const float* cb3,
                                        const float*& cb, int& K, int& coff) {
    if (e == 0)      { cb = cb0; K = 256;  coff = 0;    }
    else if (e == 1) { cb = cb1; K = 512;  coff = 256;  }
    else if (e == 2) { cb = cb2; K = 1024; coff = 768;  }
    else             { cb = cb3; K = 2048; coff = 1792; }
}

// ---------------------------------------------------------------------------
// K0a: transpose codebooks into g_cbT[c][global_k]
// ---------------------------------------------------------------------------
__global__ void transpose_kernel(const float* __restrict__ cb0, const float* __restrict__ cb1,
                                 const float* __restrict__ cb2, const float* __restrict__ cb3)
{
    int idx = blockIdx.x * 256 + threadIdx.x;
    int row = idx >> 6, c4 = idx & 63;
    const float* base; int local;
    if (row < 256)       { base = cb0; local = row;        }
    else if (row < 768)  { base = cb1; local = row - 256;  }
    else if (row < 1792) { base = cb2; local = row - 768;  }
    else                 { base = cb3; local = row - 1792; }
    float4 v = ((const float4*)(base + (size_t)local * C_DIM))[c4];
    float x[4] = {v.x, v.y, v.z, v.w};
    #pragma unroll
    for (int i = 0; i < 4; i++)
        g_cbT[(size_t)(c4 * 4 + i) * KTOT + row] = x[i];
}

// ---------------------------------------------------------------------------
// K0b: codebook row norms (fp64 -> fp32) + reset ambiguous counter
// ---------------------------------------------------------------------------
__global__ void cnorm_kernel(const float* __restrict__ cb0, const float* __restrict__ cb1,
                             const float* __restrict__ cb2, const float* __restrict__ cb3)
{
    if (blockIdx.x == 0 && threadIdx.x == 0) g_cnt = 0;
    int row  = blockIdx.x * 8 + (threadIdx.x >> 5);
    int lane = threadIdx.x & 31;
    const float* base; int local;
    if (row < 256)       { base = cb0; local = row;        }
    else if (row < 768)  { base = cb1; local = row - 256;  }
    else if (row < 1792) { base = cb2; local = row - 768;  }
    else                 { base = cb3; local = row - 1792; }
    const float4* p = (const float4*)(base + (size_t)local * C_DIM);
    double s = 0.0;
    #pragma unroll
    for (int i = 0; i < 2; i++) {
        float4 v = p[lane + i * 32];
        s += (double)v.x * v.x + (double)v.y * v.y + (double)v.z * v.z + (double)v.w * v.w;
    }
    #pragma unroll
    for (int o = 16; o; o >>= 1) s += __shfl_xor_sync(0xffffffffu, s, o);
    if (lane == 0) g_cnorm[row] = (float)s;
}

// nop: aligns the main GEMM to user-launch index 3 for the fixed ncu -s window
__global__ void nop_kernel() {}

// ---------------------------------------------------------------------------
// K1: resident-z f32x2 distance GEMM. CTA: 64 tokens x full K, 256 threads,
// 2 CTAs/SM. Thread: 8 tokens (lane&7, as 4 f32x2 pairs) x 8 codes
// (w*32 + (lane>>3)*8). B streamed in 256-code blocks, KC=8 channel stages,
// 3-stage cp.async ring, ONE barrier per stage.
// score(k) = ||c_k||^2 - 2 z.c_k ; per-token top-2 + ambiguity flags.
// ---------------------------------------------------------------------------
__global__ __launch_bounds__(256, 2) void vq_gemm(
    const float* __restrict__ z_e, const int* __restrict__ expert_idx)
{
    extern __shared__ __align__(16) char dsm[];
    const uint32_t sa = smem_u32(dsm);

    const int tid = threadIdx.x, w = tid >> 5, lane = tid & 31;
    const int lt = lane & 7;          // token group: tokens lt*8..lt*8+7
    const int lc = lane >> 3;         // code subgroup 0..3
    const int b = blockIdx.y, t0 = blockIdx.x * TOKT;

    int e = expert_idx[b];
    int K, coff;
    if (e == 0)      { K = 256;  coff = 0;    }
    else if (e == 1) { K = 512;  coff = 256;  }
    else if (e == 2) { K = 1024; coff = 768;  }
    else             { K = 2048; coff = 1792; }

    // ---- stage z resident: zs[c][t], once ----
    const float4* zin = (const float4*)(z_e + ((size_t)b * N_DIM + t0) * C_DIM);
    float* zs = (float*)dsm;
    #pragma unroll
    for (int it = 0; it < 16; it++) {
        int idx = it * 256 + tid;              // 0..4095
        int t = idx >> 6, q = idx & 63;
        float4 v = zin[t * 64 + q];
        zs[(q * 4 + 0) * TOKT + t] = v.x;
        zs[(q * 4 + 1) * TOKT + t] = v.y;
        zs[(q * 4 + 2) * TOKT + t] = v.z;
        zs[(q * 4 + 3) * TOKT + t] = v.w;
    }

    // ---- B stage: [8 ch][256 codes] = 8KB, 2 CP16/thread ----
    auto cpB = [&](int g) {
        int kb = (g >> 5) << 8;                // code block base
        int cs = (g & 31) * KC;                // channel base
        uint32_t bbuf = sa + BB_BASE + (uint32_t)((g % 3) * BB_BUF);
        const float* src0 = g_cbT + (size_t)cs * KTOT + coff + kb;
        #pragma unroll
        for (int i = 0; i < 2; i++) {
            int fid = tid * 2 + i;             // 0..511
            int cc = fid >> 6, seg = fid & 63;
            CP16(bbuf + (uint32_t)(cc * 1024 + seg * 16),
                 src0 + (size_t)cc * KTOT + seg * 4);
        }
    };

    cpB(0); CP_COMMIT();
    cpB(1); CP_COMMIT();

    unsigned long long acc[4][8];              // [token pair][code]
    float v1[8], v2[8]; int i1[8];
    #pragma unroll
    for (int r = 0; r < 8; r++) { v1[r] = 3.4e38f; v2[r] = 3.4e38f; i1[r] = 0; }

    const int cw = w * 32 + lc * 8;            // code offset within 256-block
    const int S = (K >> 8) * 32;               // 32 stages per 256-code block

    for (int s = 0; s < S; s++) {
        CP_WAIT1();                            // cp(s) complete (<=1 group pending)
        __syncthreads();                       // buf(s) visible; compute(s-1) done
        if (s + 2 < S) { cpB(s + 2); CP_COMMIT(); }   // overwrites buf(s-1): safe

        if ((s & 31) == 0) {
            #pragma unroll
            for (int tp = 0; tp < 4; tp++)
                #pragma unroll
                for (int j = 0; j < 8; j++) acc[tp][j] = 0ull;
        }

        const char* zbb = dsm + ((s & 31) * KC) * (TOKT * 4) + lt * 32;
        const char* bb  = dsm + BB_BASE + (s % 3) * BB_BUF + cw * 4;
        #pragma unroll
        for (int k = 0; k < KC; k++) {
            ulonglong2 a01 = *(const ulonglong2*)(zbb + k * (TOKT * 4));
            ulonglong2 a23 = *(const ulonglong2*)(zbb + k * (TOKT * 4) + 16);
            float4 f0 = *(const float4*)(bb + k * 1024);
            float4 f1 = *(const float4*)(bb + k * 1024 + 16);
            unsigned long long at[4] = {a01.x, a01.y, a23.x, a23.y};
            unsigned long long bd[8];
            PACKDUP(bd[0], __float_as_uint(f0.x));
            PACKDUP(bd[1], __float_as_uint(f0.y));
            PACKDUP(bd[2], __float_as_uint(f0.z));
            PACKDUP(bd[3], __float_as_uint(f0.w));
            PACKDUP(bd[4], __float_as_uint(f1.x));
            PACKDUP(bd[5], __float_as_uint(f1.y));
            PACKDUP(bd[6], __float_as_uint(f1.z));
            PACKDUP(bd[7], __float_as_uint(f1.w));
            #pragma unroll
            for (int tp = 0; tp < 4; tp++)
                #pragma unroll
                for (int j = 0; j < 8; j++)
                    FFMA2(acc[tp][j], at[tp], bd[j]);
        }

        if ((s & 31) == 31) {                  // 256-code block epilogue
            int kb = (s >> 5) << 8;
            float4 cn0 = __ldg((const float4*)(g_cnorm + coff + kb + cw));
            float4 cn1 = __ldg((const float4*)(g_cnorm + coff + kb + cw + 4));
            float cna[8] = {cn0.x, cn0.y, cn0.z, cn0.w, cn1.x, cn1.y, cn1.z, cn1.w};
            #pragma unroll
            for (int j = 0; j < 8; j++) {
                int kk = kb + cw + j;
                #pragma unroll
                for (int tp = 0; tp < 4; tp++) {
                    float lo = __uint_as_float((uint32_t)acc[tp][j]);
                    float hi = __uint_as_float((uint32_t)(acc[tp][j] >> 32));
                    float s0 = fmaf(-2.f, lo, cna[j]);
                    float s1 = fmaf(-2.f, hi, cna[j]);
                    int r0 = tp * 2, r1 = tp * 2 + 1;
                    if (s0 < v1[r0]) { v2[r0] = v1[r0]; v1[r0] = s0; i1[r0] = kk; }
                    else             { v2[r0] = fminf(v2[r0], s0); }
                    if (s1 < v1[r1]) { v2[r1] = v1[r1]; v1[r1] = s1; i1[r1] = kk; }
                    else             { v2[r1] = fminf(v2[r1], s1); }
                }
            }
        }
    }

    // merge over lc (lane bits 3,4): lanes share tokens, disjoint codes
    #pragma unroll
    for (int o = 8; o <= 16; o <<= 1) {
        #pragma unroll
        for (int r = 0; r < 8; r++) {
            float ov1 = __shfl_xor_sync(0xffffffffu, v1[r], o);
            int   oi1 = __shfl_xor_sync(0xffffffffu, i1[r], o);
            float ov2 = __shfl_xor_sync(0xffffffffu, v2[r], o);
            float hi = fmaxf(v1[r], ov1);
            float nv2 = fminf(fminf(v2[r], ov2), hi);
            if (ov1 < v1[r] || (ov1 == v1[r] && oi1 < i1[r])) { v1[r] = ov1; i1[r] = oi1; }
            v2[r] = nv2;
        }
    }

    // cross-warp merge: reduce arrays alias the (now dead) B buffers
    __syncthreads();                           // all compute done; B bufs free
    float* rv1 = (float*)(dsm + BB_BASE);
    float* rv2 = rv1 + 512;
    int*   ri1 = (int*)(rv2 + 512);
    if (lc == 0) {
        #pragma unroll
        for (int r = 0; r < 8; r++) {
            int t = lt * 8 + r;
            rv1[w * 64 + t] = v1[r];
            rv2[w * 64 + t] = v2[r];
            ri1[w * 64 + t] = i1[r];
        }
    }
    __syncthreads();
    if (tid < TOKT) {
        float bv1 = rv1[tid], bv2 = rv2[tid]; int bi1 = ri1[tid];
        #pragma unroll
        for (int ww = 1; ww < 8; ww++) {
            float ov1 = rv1[ww * 64 + tid], ov2 = rv2[ww * 64 + tid];
            int   oi1 = ri1[ww * 64 + tid];
            float hi = fmaxf(bv1, ov1);
            float nv2 = fminf(fminf(bv2, ov2), hi);
            if (ov1 < bv1 || (ov1 == bv1 && oi1 < bi1)) { bv1 = ov1; bi1 = oi1; }
            bv2 = nv2;
        }
        int tok = b * N_DIM + t0 + tid;
        g_idx[tok] = bi1;
        if (bv2 - bv1 <= EPS_AMB) {
            int pos = atomicAdd(&g_cnt, 1);
            g_amb[pos] = tok;
        }
    }
}

// ---------------------------------------------------------------------------
// K2: exact resolver (validated round 2): emulate reference fp32 rounding
// ---------------------------------------------------------------------------
__global__ __launch_bounds__(256) void resolve_kernel(
    const float* __restrict__ z_e, const int* __restrict__ expert_idx,
    const float* __restrict__ cb0, const float* __restrict__ cb1,
    const float* __restrict__ cb2, const float* __restrict__ cb3)
{
    __shared__ float zrow[8][C_DIM];
    const int wid = threadIdx.x >> 5, lane = threadIdx.x & 31;
    const int gw = blockIdx.x * 8 + wid;
    const int nw = gridDim.x * 8;
    const int cnt = g_cnt;

    for (int it = gw; it < cnt; it += nw) {
        int tok = g_amb[it];
        int b = tok >> 10;
        const float* cb; int K, coff;
        pick_cb(expert_idx[b], cb0, cb1, cb2, cb3, cb, K, coff);

        const float4* zr = (const float4*)(z_e + (size_t)tok * C_DIM);
        #pragma unroll
        for (int r = 0; r < 2; r++) {
            float4 v = zr[lane + r * 32];
            int c = (lane + r * 32) * 4;
            zrow[wid][c + 0] = v.x; zrow[wid][c + 1] = v.y;
            zrow[wid][c + 2] = v.z; zrow[wid][c + 3] = v.w;
        }
        __syncwarp();

        double zn = 0.0;
        #pragma unroll
        for (int c = 0; c < 8; c++) {
            double z = (double)zrow[wid][lane * 8 + c];
            zn += z * z;
        }
        #pragma unroll
        for (int o = 16; o; o >>= 1) zn += __shfl_xor_sync(0xffffffffu, zn, o);

        const double invGs = (zn >= 256.0) ? 32768.0 : 65536.0;
        const double Gs = 1.0 / invGs;

        double bestm = 1e300; int besti = 0x7fffffff;
        for (int k0 = 0; k0 < K; k0 += 32) {
            int k = k0 + lane;
            const float* cr = cb + (size_t)k * C_DIM;
            float acc = 0.f;
            #pragma unroll 8
            for (int c = 0; c < C_DIM; c++)
                acc = fmaf(zrow[wid][c], __ldg(&cr[c]), acc);
            float cn32 = __ldg(&g_cnorm[coff + k]);
            double dot2 = 2.0 * (double)acc;
            double d = zn + (double)cn32 - dot2;
            double invGd = (d >= 256.0) ? 32768.0 : 65536.0;
            double Gd = 1.0 / invGd;
            double m = rint((double)cn32 * invGs) * Gs - rint(dot2 * invGd) * Gd;
            if (m < bestm || (m == bestm && k < besti)) { bestm = m; besti = k; }
        }
        #pragma unroll
        for (int o = 16; o; o >>= 1) {
            double om = __shfl_xor_sync(0xffffffffu, bestm, o);
            int    oi = __shfl_xor_sync(0xffffffffu, besti, o);
            if (om < bestm || (om == bestm && oi < besti)) { bestm = om; besti = oi; }
        }
        if (lane == 0) g_idx[tok] = besti;
    }
}

// ---------------------------------------------------------------------------
// K3: gather z_q, straight-through, indices output, SSE partials
// ---------------------------------------------------------------------------
__global__ __launch_bounds__(256) void output_kernel(
    const float* __restrict__ z_e, const int* __restrict__ expert_idx,
    const float* __restrict__ cb0, const float* __restrict__ cb1,
    const float* __restrict__ cb2, const float* __restrict__ cb3,
    float* __restrict__ out)
{
    __shared__ float wsum[8];
    const int tid = threadIdx.x;
    const int b   = blockIdx.y;
    const int t0  = blockIdx.x * TOK;

    const float* cb; int K, coff;
    pick_cb(expert_idx[b], cb0, cb1, cb2, cb3, cb, K, coff);

    const float4* zin = (const float4*)(z_e + ((size_t)b * N_DIM + t0) * C_DIM);

    if (tid < TOK) {
        int idx = g_idx[b * N_DIM + t0 + tid];
        out[OUT_IDX + (size_t)b * N_DIM + t0 + tid] = (float)idx;
    }

    const int warp = tid >> 5, lane = tid & 31;
    float sq = 0.f;
    for (int s8 = 0; s8 < 8; s8++) {
        int t = warp * 8 + s8;
        int idx = g_idx[b * N_DIM + t0 + t];
        const float4* crow = (const float4*)(cb + (size_t)idx * C_DIM);
        const float4* zrow = zin + (size_t)t * 64;
        float4* orow = (float4*)(out + ((size_t)b * N_DIM + t0 + t) * C_DIM);
        #pragma unroll
        for (int r = 0; r < 2; r++) {
            int c4 = lane + r * 32;
            float4 q = crow[c4], z = zrow[c4];
            float dx = q.x - z.x, dy = q.y - z.y, dz = q.z - z.z, dw = q.w - z.w;
            sq += dx * dx + dy * dy + dz * dz + dw * dw;
            float4 o; o.x = z.x + dx; o.y = z.y + dy; o.z = z.z + dz; o.w = z.w + dw;
            orow[c4] = o;
        }
    }
    #pragma unroll
    for (int o = 16; o; o >>= 1) sq += __shfl_xor_sync(0xffffffffu, sq, o);
    if (lane == 0) wsum[warp] = sq;
    __syncthreads();
    if (tid == 0) {
        float tot = 0.f;
        #pragma unroll
        for (int w = 0; w < 8; w++) tot += wsum[w];
        g_partial[blockIdx.y * 16 + blockIdx.x] = tot;
    }
}

// ---------------------------------------------------------------------------
// K4: vq_loss = 1.25 * SSE / 2^32
// ---------------------------------------------------------------------------
__global__ void finalize_kernel(float* __restrict__ out)
{
    __shared__ float s[256];
    float a = 0.f;
    for (int i = threadIdx.x; i < 1024; i += 256) a += g_partial[i];
    s[threadIdx.x] = a;
    __syncthreads();
    for (int o = 128; o; o >>= 1) {
        if (threadIdx.x < o) s[threadIdx.x] += s[threadIdx.x + o];
        __syncthreads();
    }
    if (threadIdx.x == 0)
        out[OUT_LOSS] = s[0] * (float)(1.25 / 4294967296.0);
}

// ---------------------------------------------------------------------------
extern "C" void kernel_launch(void* const* d_in, const int* in_sizes, int n_in,
                              void* d_out, int out_size)
{
    const float* z_e        = (const float*)d_in[0];
    const int*   expert_idx = (const int*)  d_in[1];
    const float* cb0        = (const float*)d_in[2];
    const float* cb1        = (const float*)d_in[3];
    const float* cb2        = (const float*)d_in[4];
    const float* cb3        = (const float*)d_in[5];
    float* out = (float*)d_out;

    cudaFuncSetAttribute(vq_gemm, cudaFuncAttributeMaxDynamicSharedMemorySize, SM_DYN);

    transpose_kernel<<<960, 256>>>(cb0, cb1, cb2, cb3);   // user launch 0
    cnorm_kernel<<<480, 256>>>(cb0, cb1, cb2, cb3);       // user launch 1
    nop_kernel<<<1, 32>>>();                              // user launch 2 (ncu align)

    dim3 gmain(N_DIM / TOKT, B_DIM);
    vq_gemm<<<gmain, 256, SM_DYN>>>(z_e, expert_idx);     // user launch 3 -> profiled

    resolve_kernel<<<128, 256>>>(z_e, expert_idx, cb0, cb1, cb2, cb3);

    dim3 gout(N_DIM / TOK, B_DIM);
    output_kernel<<<gout, 256>>>(z_e, expert_idx, cb0, cb1, cb2, cb3, out);

    finalize_kernel<<<1, 256>>>(out);
}